// round 5
// baseline (speedup 1.0000x reference)
#include <cuda_runtime.h>
#include <cstdint>

// ---------------------------------------------------------------------------
// Problem constants
// ---------------------------------------------------------------------------
#define BSZ   8192
#define MT    128           // batch rows per CTA tile
#define THR   256

// ---------------------------------------------------------------------------
// Device scratch (allocation-free rule: __device__ globals)
// ---------------------------------------------------------------------------
__device__ __align__(256) float g_S [(size_t)64 * 64 * BSZ];   // [(n*64+m)][b]  layer0 -> layer1
__device__ __align__(256) float g_S2[(size_t)4096 * BSZ];      // [f][b]         layer1 -> transpose

// ---------------------------------------------------------------------------
// SMEM layout (float offsets)
// ---------------------------------------------------------------------------
#define PA    136
#define PW1   136
#define PW2   72
#define PH    136
#define PST   69

#define OFF_A    0              // 64 x 136            = 8704
#define OFF_W1   8704           // 64 x 136            = 8704
#define OFF_W2   17408          // 128 x 72            = 9216
#define OFF_H    26624          // 128 x 136           = 17408
#define OFF_ST   26624          // 128 x 69 = 8832 (overlay on H; used before H)
#define OFF_B1   44032          // 128
#define OFF_B2   44160          // 64
#define SMEM_FLOATS 44224
#define SMEM_BYTES  (SMEM_FLOATS * 4)

// ---------------------------------------------------------------------------
// Helpers (NO sm_103a-only instructions anywhere)
// ---------------------------------------------------------------------------
static __device__ __forceinline__ uint32_t f2tf(float f) {
    uint32_t u;
    asm("cvt.rna.tf32.f32 %0, %1;" : "=r"(u) : "f"(f));
    return u;
}
static __device__ __forceinline__ float rna_tf32(float f) {
    return __uint_as_float(f2tf(f));
}
// D += A(16x8) * B(8x8), tf32, row.col
static __device__ __forceinline__ void mma8(float* d, const uint32_t* a,
                                            uint32_t b0, uint32_t b1) {
    asm volatile(
        "mma.sync.aligned.m16n8k8.row.col.f32.tf32.tf32.f32 "
        "{%0,%1,%2,%3},{%4,%5,%6,%7},{%8,%9},{%0,%1,%2,%3};"
        : "+f"(d[0]), "+f"(d[1]), "+f"(d[2]), "+f"(d[3])
        : "r"(a[0]), "r"(a[1]), "r"(a[2]), "r"(a[3]), "r"(b0), "r"(b1));
}

// ---------------------------------------------------------------------------
// Layer kernel. layer==0: x -> g_S ; layer==1: g_S -> g_S2
// Grid: (64 batch tiles, 64 blocks), 256 threads, 8 warps.
// Warp partition of C (128 x N): (wid&3) -> 32-row m-band, (wid>>2) -> col half.
// ---------------------------------------------------------------------------
__global__ void __launch_bounds__(THR)
layer_kernel(int layer, const float* __restrict__ x,
             const float* __restrict__ w1g, const float* __restrict__ b1g,
             const float* __restrict__ w2g, const float* __restrict__ b2g) {
    extern __shared__ float sm[];
    float* sA  = sm + OFF_A;
    float* sW1 = sm + OFF_W1;
    float* sW2 = sm + OFF_W2;
    float* sH  = sm + OFF_H;
    float* sSt = sm + OFF_ST;
    float* sb1 = sm + OFF_B1;
    float* sb2 = sm + OFF_B2;

    const int t    = threadIdx.x;
    const int wid  = t >> 5;
    const int lane = t & 31;
    const int g    = lane >> 2;     // groupID (0..7)
    const int tig  = lane & 3;      // threadID in group (0..3)
    const int blk  = blockIdx.y;
    const int b0   = blockIdx.x * MT;
    const int ln   = layer * 64 + blk;

    // ---- biases
    if (t < 128)                sb1[t]       = b1g[(size_t)ln * 128 + t];
    else if (t < 192)           sb2[t - 128] = b2g[(size_t)ln * 64 + (t - 128)];

    // ---- W1 [d=64][e=128] -> sW1[d][e] (rna-rounded)
    {
        const float4* src = (const float4*)(w1g + (size_t)ln * 8192);
#pragma unroll
        for (int i = 0; i < 8; i++) {
            int idx = i * THR + t;          // 2048 float4
            int d = idx >> 5, e4 = idx & 31;
            float4 v = src[d * 32 + e4];
            float4 r;
            r.x = rna_tf32(v.x); r.y = rna_tf32(v.y);
            r.z = rna_tf32(v.z); r.w = rna_tf32(v.w);
            *(float4*)(sW1 + d * PW1 + e4 * 4) = r;
        }
    }
    // ---- W2 [e=128][d=64] -> sW2[e][d] (rna-rounded)
    {
        const float4* src = (const float4*)(w2g + (size_t)ln * 8192);
#pragma unroll
        for (int i = 0; i < 8; i++) {
            int idx = i * THR + t;          // 2048 float4
            int e = idx >> 4, d4 = idx & 15;
            float4 v = src[e * 16 + d4];
            float4 r;
            r.x = rna_tf32(v.x); r.y = rna_tf32(v.y);
            r.z = rna_tf32(v.z); r.w = rna_tf32(v.w);
            *(float4*)(sW2 + e * PW2 + d4 * 4) = r;
        }
    }

    // ---- A tile -> sA[k=64][b=128] (EXACT values; rounding at fragment load)
    if (layer == 0) {
        // stage x[b][k] coalesced, then smem-transpose into sA[k][b]
#pragma unroll
        for (int i = 0; i < 8; i++) {
            int idx = i * THR + t;          // 2048 float4 = 128 b x 16 k4
            int b = idx >> 4, k4 = idx & 15;
            float4 v = *(const float4*)(x + (size_t)(b0 + b) * 4096 + blk * 64 + k4 * 4);
            float* d = sSt + b * PST + k4 * 4;
            d[0] = v.x; d[1] = v.y; d[2] = v.z; d[3] = v.w;
        }
        __syncthreads();
#pragma unroll
        for (int i = 0; i < 32; i++) {
            int idx = i * THR + t;          // 8192 = 64 k x 128 b
            int k = idx >> 7, b = idx & 127;
            sA[k * PA + b] = sSt[b * PST + k];
        }
    } else {
        // g_S rows are [k=d][b] already -> direct coalesced copy
#pragma unroll
        for (int i = 0; i < 8; i++) {
            int idx = i * THR + t;          // 2048 float4 = 64 d x 32 b4
            int d = idx >> 5, b4 = idx & 31;
            float4 v = *(const float4*)(g_S + ((size_t)blk * 64 + d) * BSZ + b0 + b4 * 4);
            *(float4*)(sA + d * PA + b4 * 4) = v;
        }
    }
    __syncthreads();

    const int mq = wid & 3;                 // m-band: rows [32*mq, 32*mq+32)
    const int ch = wid >> 2;                // column half
    const int m0 = mq * 32;

    // =======================================================================
    // GEMM1: C1[128 x 128] = A[128 x 64] * W1[64 x 128]
    // warp: 32 rows x 64 cols; mt 0..1, nt 0..7, kt 0..7
    // =======================================================================
    uint32_t au[2][8][4];
#pragma unroll
    for (int mt = 0; mt < 2; mt++) {
        int r = m0 + mt * 16 + g;
#pragma unroll
        for (int kt = 0; kt < 8; kt++) {
            int k = kt * 8 + tig;
            au[mt][kt][0] = f2tf(sA[k * PA + r]);
            au[mt][kt][1] = f2tf(sA[k * PA + r + 8]);
            au[mt][kt][2] = f2tf(sA[(k + 4) * PA + r]);
            au[mt][kt][3] = f2tf(sA[(k + 4) * PA + r + 8]);
        }
    }
    float acc1[2][8][4];
#pragma unroll
    for (int mt = 0; mt < 2; mt++)
#pragma unroll
        for (int nt = 0; nt < 8; nt++)
#pragma unroll
            for (int c = 0; c < 4; c++) acc1[mt][nt][c] = 0.f;

#pragma unroll
    for (int nt = 0; nt < 8; nt++) {
        int ecol = ch * 64 + nt * 8 + g;
#pragma unroll
        for (int kt = 0; kt < 8; kt++) {
            int k = kt * 8 + tig;
            uint32_t bb0 = __float_as_uint(sW1[k * PW1 + ecol]);
            uint32_t bb1 = __float_as_uint(sW1[(k + 4) * PW1 + ecol]);
            mma8(acc1[0][nt], au[0][kt], bb0, bb1);
            mma8(acc1[1][nt], au[1][kt], bb0, bb1);
        }
    }

    // ---- Epilogue 1: bias + ELU, store H[e][b] (rounded; it's GEMM2's A op)
#pragma unroll
    for (int mt = 0; mt < 2; mt++) {
#pragma unroll
        for (int nt = 0; nt < 8; nt++) {
#pragma unroll
            for (int c = 0; c < 4; c++) {
                int row = m0 + mt * 16 + g + 8 * (c >> 1);
                int e   = ch * 64 + nt * 8 + tig * 2 + (c & 1);
                float h = acc1[mt][nt][c] + sb1[e];
                h = (h > 0.f) ? h : (__expf(h) - 1.f);
                sH[e * PH + row] = rna_tf32(h);
            }
        }
    }
    __syncthreads();

    // =======================================================================
    // GEMM2: C2[128 x 64] = H[128 x 128] * W2[128 x 64]
    // warp: 32 rows x 32 cols; mt 0..1, nt 0..3, kt 0..15 (chunked by 8)
    // =======================================================================
    float acc2[2][4][4];
#pragma unroll
    for (int mt = 0; mt < 2; mt++)
#pragma unroll
        for (int nt = 0; nt < 4; nt++)
#pragma unroll
            for (int c = 0; c < 4; c++) acc2[mt][nt][c] = 0.f;

#pragma unroll
    for (int ktc = 0; ktc < 2; ktc++) {
        uint32_t a2[2][8][4];
#pragma unroll
        for (int mt = 0; mt < 2; mt++) {
            int r = m0 + mt * 16 + g;
#pragma unroll
            for (int kt = 0; kt < 8; kt++) {
                int k = ktc * 64 + kt * 8 + tig;
                a2[mt][kt][0] = __float_as_uint(sH[k * PH + r]);
                a2[mt][kt][1] = __float_as_uint(sH[k * PH + r + 8]);
                a2[mt][kt][2] = __float_as_uint(sH[(k + 4) * PH + r]);
                a2[mt][kt][3] = __float_as_uint(sH[(k + 4) * PH + r + 8]);
            }
        }
#pragma unroll
        for (int nt = 0; nt < 4; nt++) {
            int dcol = ch * 32 + nt * 8 + g;
#pragma unroll
            for (int kt = 0; kt < 8; kt++) {
                int k = ktc * 64 + kt * 8 + tig;
                uint32_t bb0 = __float_as_uint(sW2[k * PW2 + dcol]);
                uint32_t bb1 = __float_as_uint(sW2[(k + 4) * PW2 + dcol]);
                mma8(acc2[0][nt], a2[0][kt], bb0, bb1);
                mma8(acc2[1][nt], a2[1][kt], bb0, bb1);
            }
        }
    }

    // ---- Epilogue 2: bias + residual (exact z from sA) + 32B-contiguous STG
#pragma unroll
    for (int mt = 0; mt < 2; mt++) {
#pragma unroll
        for (int nt = 0; nt < 4; nt++) {
#pragma unroll
            for (int c = 0; c < 4; c++) {
                int row = m0 + mt * 16 + g + 8 * (c >> 1);
                int d   = ch * 32 + nt * 8 + tig * 2 + (c & 1);
                float z = sA[d * PA + row];
                float v = acc2[mt][nt][c] + sb2[d] + z;
                if (layer == 0)
                    g_S [((size_t)d * 64 + blk) * BSZ + b0 + row] = v;   // [n=d][m=blk][b]
                else
                    g_S2[((size_t)d * 64 + blk) * BSZ + b0 + row] = v;   // [f=d*64+n][b]
            }
        }
    }
}

// ---------------------------------------------------------------------------
// Final transpose: out[b][f] = g_S2[f][b]   (4096 x 8192 -> 8192 x 4096)
// ---------------------------------------------------------------------------
__global__ void __launch_bounds__(256)
transpose_kernel(float* __restrict__ out) {
    __shared__ float tile[64 * 68];
    const int f0 = blockIdx.x * 64, bb0 = blockIdx.y * 64;
    const int t = threadIdx.x;
#pragma unroll
    for (int p = 0; p < 4; p++) {
        int idx = p * 256 + t;              // 1024 float4 = 64 f x 16 b4
        int f = idx >> 4, b4 = idx & 15;
        float4 v = *(const float4*)(g_S2 + (size_t)(f0 + f) * BSZ + bb0 + b4 * 4);
        float* d = tile + f * 68 + b4 * 4;
        d[0] = v.x; d[1] = v.y; d[2] = v.z; d[3] = v.w;
    }
    __syncthreads();
#pragma unroll
    for (int p = 0; p < 4; p++) {
        int idx = p * 256 + t;              // 1024 float4 = 64 b x 16 f4
        int b = idx >> 4, f4 = idx & 15;
        float4 v;
        v.x = tile[(f4 * 4 + 0) * 68 + b];
        v.y = tile[(f4 * 4 + 1) * 68 + b];
        v.z = tile[(f4 * 4 + 2) * 68 + b];
        v.w = tile[(f4 * 4 + 3) * 68 + b];
        *(float4*)(out + (size_t)(bb0 + b) * 4096 + f0 + f4 * 4) = v;
    }
}

// ---------------------------------------------------------------------------
// kernel_launch
// ---------------------------------------------------------------------------
extern "C" void kernel_launch(void* const* d_in, const int* in_sizes, int n_in,
                              void* d_out, int out_size) {
    const float* x  = (const float*)d_in[0];
    const float* w1 = (const float*)d_in[1];
    const float* b1 = (const float*)d_in[2];
    const float* w2 = (const float*)d_in[3];
    const float* b2 = (const float*)d_in[4];
    float* out = (float*)d_out;
    (void)in_sizes; (void)n_in; (void)out_size;

    static int configured = 0;
    // cudaFuncSetAttribute is a host-side attribute set (not a stream op);
    // calling it every time is deterministic and capture-safe.
    cudaFuncSetAttribute(layer_kernel, cudaFuncAttributeMaxDynamicSharedMemorySize, SMEM_BYTES);
    (void)configured;

    layer_kernel<<<dim3(64, 64), THR, SMEM_BYTES>>>(0, x, w1, b1, w2, b2);
    layer_kernel<<<dim3(64, 64), THR, SMEM_BYTES>>>(1, x, w1, b1, w2, b2);
    transpose_kernel<<<dim3(64, 128), 256>>>(out);
}

// round 9
// speedup vs baseline: 1.5764x; 1.5764x over previous
#include <cuda_runtime.h>
#include <cstdint>

// ---------------------------------------------------------------------------
// Problem constants
// ---------------------------------------------------------------------------
#define BSZ   8192
#define MT    128           // batch rows per CTA tile
#define THR   256

// ---------------------------------------------------------------------------
// Device scratch (allocation-free rule: __device__ globals)
// ---------------------------------------------------------------------------
// Exchange layout: g_S[(d*64 + m)][b]  (layer-0 block m, out-dim d, batch b).
// Layer-1 block n reads rows (n*64 + c) for c=0..63  ->  contiguous in b.
__device__ __align__(256) float g_S [(size_t)4096 * BSZ];
__device__ __align__(256) float g_S2[(size_t)4096 * BSZ];      // [f][b] -> transpose

// ---------------------------------------------------------------------------
// SMEM layout (float offsets)
// ---------------------------------------------------------------------------
#define PAB   68            // layer0: sA [b=128][k=64] pitch 68  (frag bank 4g+tig)
#define PAK   136           // layer1: sA [k=64][b=128] pitch 136 (frag bank 8tig+g)
#define PW1   136           // sW1 [k=64][e=128]  pitch 136 -> frag bank 8tig+g
#define PW2   72            // sW2 [k=128][d=64]  pitch 72  -> frag bank 8tig+g

#define OFF_A    0                          // 8704 floats (both layouts)
#define OFF_W1   (OFF_A  + 8704)            // 64*136  = 8704
#define OFF_W2   (OFF_W1 + 64 * PW1)        // 128*72  = 9216
#define OFF_B1   (OFF_W2 + 128 * PW2)       // 128
#define OFF_B2   (OFF_B1 + 128)             // 64
#define SMEM_FLOATS (OFF_B2 + 64)
#define SMEM_BYTES  (SMEM_FLOATS * 4)       // 107,264 B -> 2 CTAs/SM

// ---------------------------------------------------------------------------
// Helpers (no sm_103a-only instructions)
// ---------------------------------------------------------------------------
static __device__ __forceinline__ uint32_t f2tf(float f) {
    uint32_t u;
    asm("cvt.rna.tf32.f32 %0, %1;" : "=r"(u) : "f"(f));
    return u;
}
static __device__ __forceinline__ float rna_tf32(float f) {
    return __uint_as_float(f2tf(f));
}
// D += A(16x8) * B(8x8), tf32, row.col
static __device__ __forceinline__ void mma8(float* d, const uint32_t* a,
                                            uint32_t b0, uint32_t b1) {
    asm volatile(
        "mma.sync.aligned.m16n8k8.row.col.f32.tf32.tf32.f32 "
        "{%0,%1,%2,%3},{%4,%5,%6,%7},{%8,%9},{%0,%1,%2,%3};"
        : "+f"(d[0]), "+f"(d[1]), "+f"(d[2]), "+f"(d[3])
        : "r"(a[0]), "r"(a[1]), "r"(a[2]), "r"(a[3]), "r"(b0), "r"(b1));
}

// ---------------------------------------------------------------------------
// Layer kernel (templated on LAYER; branch-free instantiations).
// Grid: (64 batch tiles, 64 blocks), 256 threads, 8 warps.
// Each warp owns 16 batch rows x ALL columns -> one barrier total.
// ---------------------------------------------------------------------------
template <int LAYER>
__global__ void __launch_bounds__(THR, 2)
layer_kernel(const float* __restrict__ x,
             const float* __restrict__ w1g, const float* __restrict__ b1g,
             const float* __restrict__ w2g, const float* __restrict__ b2g) {
    extern __shared__ float sm[];
    float* sA  = sm + OFF_A;
    float* sW1 = sm + OFF_W1;
    float* sW2 = sm + OFF_W2;
    float* sb1 = sm + OFF_B1;
    float* sb2 = sm + OFF_B2;

    const int t    = threadIdx.x;
    const int wid  = t >> 5;
    const int lane = t & 31;
    const int g    = lane >> 2;     // groupID (0..7)
    const int tig  = lane & 3;      // thread-in-group (0..3)
    const int blk  = blockIdx.y;
    const int b0   = blockIdx.x * MT;
    const int ln   = LAYER * 64 + blk;

    // ---- biases
    if (t < 128)      sb1[t]       = b1g[(size_t)ln * 128 + t];
    else if (t < 192) sb2[t - 128] = b2g[(size_t)ln * 64 + (t - 128)];

    // ---- W1 [d=64][e=128] -> sW1[k=d][e] (rna-rounded)
    {
        const float4* src = (const float4*)(w1g + (size_t)ln * 8192);
#pragma unroll
        for (int i = 0; i < 8; i++) {
            int idx = i * THR + t;          // 2048 float4
            int d = idx >> 5, e4 = idx & 31;
            float4 v = src[idx];
            float4 r;
            r.x = rna_tf32(v.x); r.y = rna_tf32(v.y);
            r.z = rna_tf32(v.z); r.w = rna_tf32(v.w);
            *(float4*)(sW1 + d * PW1 + e4 * 4) = r;
        }
    }
    // ---- W2 [e=128][d=64] -> sW2[k=e][d] (rna-rounded)
    {
        const float4* src = (const float4*)(w2g + (size_t)ln * 8192);
#pragma unroll
        for (int i = 0; i < 8; i++) {
            int idx = i * THR + t;          // 2048 float4
            int e = idx >> 4, d4 = idx & 15;
            float4 v = src[idx];
            float4 r;
            r.x = rna_tf32(v.x); r.y = rna_tf32(v.y);
            r.z = rna_tf32(v.z); r.w = rna_tf32(v.w);
            *(float4*)(sW2 + e * PW2 + d4 * 4) = r;
        }
    }
    // ---- A tile (EXACT values; rounded at fragment load)
    if (LAYER == 0) {
        // x rows are [b][k]: direct coalesced copy -> sA[b][k]
#pragma unroll
        for (int i = 0; i < 8; i++) {
            int idx = i * THR + t;          // 2048 float4 = 128 b x 16 k4
            int b = idx >> 4, k4 = idx & 15;
            float4 v = *(const float4*)(x + (size_t)(b0 + b) * 4096 + blk * 64 + k4 * 4);
            *(float4*)(sA + b * PAB + k4 * 4) = v;
        }
    } else {
        // g_S rows (blk*64 + k) are [k][b]: direct coalesced copy -> sA[k][b]
#pragma unroll
        for (int i = 0; i < 8; i++) {
            int idx = i * THR + t;          // 2048 float4 = 64 k x 32 b4
            int k = idx >> 5, b4 = idx & 31;
            float4 v = *(const float4*)(g_S + ((size_t)blk * 64 + k) * BSZ + b0 + b4 * 4);
            *(float4*)(sA + k * PAK + b4 * 4) = v;
        }
    }
    __syncthreads();
    // ======= from here on: warps fully independent =======

    const int m0 = wid * 16;                // this warp's 16-row band
    const int r0 = m0 + g;                  // fragment rows r0, r0+8

    // ---- GEMM1 A-fragments (rounded once)
    uint32_t au[8][4];
#pragma unroll
    for (int kt = 0; kt < 8; kt++) {
        int k = kt * 8 + tig;
        if (LAYER == 0) {
            au[kt][0] = f2tf(sA[r0 * PAB + k]);
            au[kt][1] = f2tf(sA[(r0 + 8) * PAB + k]);
            au[kt][2] = f2tf(sA[r0 * PAB + k + 4]);
            au[kt][3] = f2tf(sA[(r0 + 8) * PAB + k + 4]);
        } else {
            au[kt][0] = f2tf(sA[k * PAK + r0]);
            au[kt][1] = f2tf(sA[k * PAK + r0 + 8]);
            au[kt][2] = f2tf(sA[(k + 4) * PAK + r0]);
            au[kt][3] = f2tf(sA[(k + 4) * PAK + r0 + 8]);
        }
    }

    // ---- GEMM1: C1[16 x 128] = A[16 x 64] * W1[64 x 128]
    float acc1[16][4];
#pragma unroll
    for (int nt = 0; nt < 16; nt++)
#pragma unroll
        for (int c = 0; c < 4; c++) acc1[nt][c] = 0.f;

#pragma unroll
    for (int kt = 0; kt < 8; kt++) {
        int k = kt * 8 + tig;
#pragma unroll
        for (int nt = 0; nt < 16; nt++) {
            int e = nt * 8 + g;
            uint32_t bb0 = __float_as_uint(sW1[k * PW1 + e]);
            uint32_t bb1 = __float_as_uint(sW1[(k + 4) * PW1 + e]);
            mma8(acc1[nt], au[kt], bb0, bb1);
        }
    }

    // ---- GEMM2: per k-block: bias+ELU+round on C1 frag, quad-shuffle into
    //      A-fragment layout, accumulate C2[16 x 64].  (verified lane math)
    float acc2[8][4];
#pragma unroll
    for (int nt = 0; nt < 8; nt++)
#pragma unroll
        for (int c = 0; c < 4; c++) acc2[nt][c] = 0.f;

    const int qbase = lane & ~3;            // quad base lane
    const int s0 = qbase | (tig >> 1);      // src lane for col tig
    const int s2 = s0 | 2;                  // src lane for col tig+4
    const bool odd = (tig & 1);

#pragma unroll
    for (int kb = 0; kb < 16; kb++) {
        float bb0 = sb1[kb * 8 + tig * 2];
        float bb1 = sb1[kb * 8 + tig * 2 + 1];
        float h0 = acc1[kb][0] + bb0;       // (r0,   2tig)
        float h1 = acc1[kb][1] + bb1;       // (r0,   2tig+1)
        float h2 = acc1[kb][2] + bb0;       // (r0+8, 2tig)
        float h3 = acc1[kb][3] + bb1;       // (r0+8, 2tig+1)
        h0 = rna_tf32(h0 > 0.f ? h0 : (__expf(h0) - 1.f));
        h1 = rna_tf32(h1 > 0.f ? h1 : (__expf(h1) - 1.f));
        h2 = rna_tf32(h2 > 0.f ? h2 : (__expf(h2) - 1.f));
        h3 = rna_tf32(h3 > 0.f ? h3 : (__expf(h3) - 1.f));

        uint32_t a2f[4];
        {
            float p0 = __shfl_sync(0xffffffffu, h0, s0);
            float p1 = __shfl_sync(0xffffffffu, h1, s0);
            float q0 = __shfl_sync(0xffffffffu, h2, s0);
            float q1 = __shfl_sync(0xffffffffu, h3, s0);
            float r0f = __shfl_sync(0xffffffffu, h0, s2);
            float r1f = __shfl_sync(0xffffffffu, h1, s2);
            float u0 = __shfl_sync(0xffffffffu, h2, s2);
            float u1 = __shfl_sync(0xffffffffu, h3, s2);
            a2f[0] = __float_as_uint(odd ? p1 : p0);   // (r0,   tig)
            a2f[1] = __float_as_uint(odd ? q1 : q0);   // (r0+8, tig)
            a2f[2] = __float_as_uint(odd ? r1f : r0f); // (r0,   tig+4)
            a2f[3] = __float_as_uint(odd ? u1 : u0);   // (r0+8, tig+4)
        }

        int k = kb * 8 + tig;
#pragma unroll
        for (int nt = 0; nt < 8; nt++) {
            int d = nt * 8 + g;
            uint32_t w0 = __float_as_uint(sW2[k * PW2 + d]);
            uint32_t w1v = __float_as_uint(sW2[(k + 4) * PW2 + d]);
            mma8(acc2[nt], a2f, w0, w1v);
        }
    }

    // ---- Epilogue 2: bias + residual (exact z from sA) + stores
    // Both layers: scalar stores, each quad packs full 32B sectors.
#pragma unroll
    for (int nt = 0; nt < 8; nt++) {
#pragma unroll
        for (int c = 0; c < 4; c++) {
            int row = r0 + 8 * (c >> 1);
            int d   = nt * 8 + tig * 2 + (c & 1);
            float z = (LAYER == 0) ? sA[row * PAB + d] : sA[d * PAK + row];
            float v = acc2[nt][c] + sb2[d] + z;
            if (LAYER == 0)
                g_S [((size_t)d * 64 + blk) * BSZ + b0 + row] = v;   // [d][m=blk][b]
            else
                g_S2[((size_t)d * 64 + blk) * BSZ + b0 + row] = v;   // [f=d*64+blk][b]
        }
    }
}

// ---------------------------------------------------------------------------
// Final transpose: out[b][f] = g_S2[f][b]   (4096 x 8192 -> 8192 x 4096)
// ---------------------------------------------------------------------------
__global__ void __launch_bounds__(256)
transpose_kernel(float* __restrict__ out) {
    __shared__ float tile[64 * 68];
    const int f0 = blockIdx.x * 64, bb0 = blockIdx.y * 64;
    const int t = threadIdx.x;
#pragma unroll
    for (int p = 0; p < 4; p++) {
        int idx = p * 256 + t;              // 1024 float4 = 64 f x 16 b4
        int f = idx >> 4, b4 = idx & 15;
        float4 v = *(const float4*)(g_S2 + (size_t)(f0 + f) * BSZ + bb0 + b4 * 4);
        float* d = tile + f * 68 + b4 * 4;
        d[0] = v.x; d[1] = v.y; d[2] = v.z; d[3] = v.w;
    }
    __syncthreads();
#pragma unroll
    for (int p = 0; p < 4; p++) {
        int idx = p * 256 + t;              // 1024 float4 = 64 b x 16 f4
        int b = idx >> 4, f4 = idx & 15;
        float4 v;
        v.x = tile[(f4 * 4 + 0) * 68 + b];
        v.y = tile[(f4 * 4 + 1) * 68 + b];
        v.z = tile[(f4 * 4 + 2) * 68 + b];
        v.w = tile[(f4 * 4 + 3) * 68 + b];
        *(float4*)(out + (size_t)(bb0 + b) * 4096 + f0 + f4 * 4) = v;
    }
}

// ---------------------------------------------------------------------------
// kernel_launch
// ---------------------------------------------------------------------------
extern "C" void kernel_launch(void* const* d_in, const int* in_sizes, int n_in,
                              void* d_out, int out_size) {
    const float* x  = (const float*)d_in[0];
    const float* w1 = (const float*)d_in[1];
    const float* b1 = (const float*)d_in[2];
    const float* w2 = (const float*)d_in[3];
    const float* b2 = (const float*)d_in[4];
    float* out = (float*)d_out;
    (void)in_sizes; (void)n_in; (void)out_size;

    cudaFuncSetAttribute(layer_kernel<0>, cudaFuncAttributeMaxDynamicSharedMemorySize, SMEM_BYTES);
    cudaFuncSetAttribute(layer_kernel<1>, cudaFuncAttributeMaxDynamicSharedMemorySize, SMEM_BYTES);

    layer_kernel<0><<<dim3(64, 64), THR, SMEM_BYTES>>>(x, w1, b1, w2, b2);
    layer_kernel<1><<<dim3(64, 64), THR, SMEM_BYTES>>>(x, w1, b1, w2, b2);
    transpose_kernel<<<dim3(64, 128), 256>>>(out);
}

// round 11
// speedup vs baseline: 2.2758x; 1.4437x over previous
#include <cuda_runtime.h>
#include <cstdint>

// ---------------------------------------------------------------------------
// Problem constants
// ---------------------------------------------------------------------------
#define BSZ   8192
#define MT    256           // batch rows per CTA tile
#define THR   256

// ---------------------------------------------------------------------------
// Device scratch (allocation-free rule: __device__ globals)
// ---------------------------------------------------------------------------
// Exchange: g_S[(d*64 + m)][b]  (layer-0 block m, out-dim d, batch b).
// Layer-1 block n reads rows (n*64 + c), c=0..63 -> contiguous in b.
__device__ __align__(256) float g_S [(size_t)4096 * BSZ];
__device__ __align__(256) float g_S2[(size_t)4096 * BSZ];      // [f][b] -> transpose

// ---------------------------------------------------------------------------
// SMEM layout (float offsets)
// ---------------------------------------------------------------------------
#define PAB   68            // layer0: sA [b=256][k=64]  pitch 68  (frag bank 4g+tig)
#define PAK   264           // layer1: sA [k=64][b=256]  pitch 264 (frag bank 8tig+g)
#define PW1P  132           // sW1p [p=32][e=128] float2, pitch 132 f2 (bank 4tig+g CF)
#define PW2P  68            // sW2p [p=64][d=64]  float2, pitch 68 f2  (bank 4tig+g CF)

#define OFF_A    0                          // max(256*68, 64*264) = 17408 floats
#define OFF_W1   17408                      // 32*132 f2 = 8448 floats
#define OFF_W2   (OFF_W1 + 32 * PW1P * 2)   // 64*68 f2  = 8704 floats
#define OFF_B1   (OFF_W2 + 64 * PW2P * 2)
#define OFF_B2   (OFF_B1 + 128)
#define SMEM_FLOATS (OFF_B2 + 64)
#define SMEM_BYTES  (SMEM_FLOATS * 4)       // 139,008 B -> 1 CTA/SM

// ---------------------------------------------------------------------------
// Helpers (no sm_103a-only instructions)
// ---------------------------------------------------------------------------
static __device__ __forceinline__ uint32_t f2tf(float f) {
    uint32_t u;
    asm("cvt.rna.tf32.f32 %0, %1;" : "=r"(u) : "f"(f));
    return u;
}
static __device__ __forceinline__ float rna_tf32(float f) {
    return __uint_as_float(f2tf(f));
}
// D += A(16x8) * B(8x8), tf32, row.col
static __device__ __forceinline__ void mma8(float* d, const uint32_t* a,
                                            uint32_t b0, uint32_t b1) {
    asm volatile(
        "mma.sync.aligned.m16n8k8.row.col.f32.tf32.tf32.f32 "
        "{%0,%1,%2,%3},{%4,%5,%6,%7},{%8,%9},{%0,%1,%2,%3};"
        : "+f"(d[0]), "+f"(d[1]), "+f"(d[2]), "+f"(d[3])
        : "r"(a[0]), "r"(a[1]), "r"(a[2]), "r"(a[3]), "r"(b0), "r"(b1));
}

// ---------------------------------------------------------------------------
// Layer kernel. Grid: (32 batch tiles, 64 blocks), 256 threads, 8 warps.
// Each warp owns 32 batch rows (2 m-tiles) x ALL columns; GEMM1->GEMM2 fused
// per 8-wide e-block so acc1 never materializes.
// ---------------------------------------------------------------------------
template <int LAYER>
__global__ void __launch_bounds__(THR, 1)
layer_kernel(const float* __restrict__ x,
             const float* __restrict__ w1g, const float* __restrict__ b1g,
             const float* __restrict__ w2g, const float* __restrict__ b2g) {
    extern __shared__ float sm[];
    float*  sA   = sm + OFF_A;
    float2* sW1p = (float2*)(sm + OFF_W1);
    float2* sW2p = (float2*)(sm + OFF_W2);
    float*  sb1  = sm + OFF_B1;
    float*  sb2  = sm + OFF_B2;

    const int t    = threadIdx.x;
    const int wid  = t >> 5;
    const int lane = t & 31;
    const int g    = lane >> 2;     // groupID (0..7)
    const int tig  = lane & 3;      // thread-in-group (0..3)
    const int blk  = blockIdx.y;
    const int b0   = blockIdx.x * MT;
    const int ln   = LAYER * 64 + blk;

    // ---- biases
    if (t < 128)      sb1[t]       = b1g[(size_t)ln * 128 + t];
    else if (t < 192) sb2[t - 128] = b2g[(size_t)ln * 64 + (t - 128)];

    // ---- W1 [k=64][e=128] -> paired-k float2 sW1p[p=kt*4+tig'][e]
    {
        const float4* src = (const float4*)(w1g + (size_t)ln * 8192);
#pragma unroll
        for (int i = 0; i < 4; i++) {
            int idx = i * THR + t;          // 1024 = 32 p x 32 e4
            int p = idx >> 5, e4 = idx & 31;
            int klo = (p >> 2) * 8 + (p & 3);
            float4 vlo = src[klo * 32 + e4];
            float4 vhi = src[(klo + 4) * 32 + e4];
            float2* dst = sW1p + p * PW1P + e4 * 4;
            dst[0] = make_float2(rna_tf32(vlo.x), rna_tf32(vhi.x));
            dst[1] = make_float2(rna_tf32(vlo.y), rna_tf32(vhi.y));
            dst[2] = make_float2(rna_tf32(vlo.z), rna_tf32(vhi.z));
            dst[3] = make_float2(rna_tf32(vlo.w), rna_tf32(vhi.w));
        }
    }
    // ---- W2 [k=128][d=64] -> paired-k float2 sW2p[p=kb*4+tig'][d]
    {
        const float4* src = (const float4*)(w2g + (size_t)ln * 8192);
#pragma unroll
        for (int i = 0; i < 4; i++) {
            int idx = i * THR + t;          // 1024 = 64 p x 16 d4
            int p = idx >> 4, d4 = idx & 15;
            int klo = (p >> 2) * 8 + (p & 3);
            float4 vlo = src[klo * 16 + d4];
            float4 vhi = src[(klo + 4) * 16 + d4];
            float2* dst = sW2p + p * PW2P + d4 * 4;
            dst[0] = make_float2(rna_tf32(vlo.x), rna_tf32(vhi.x));
            dst[1] = make_float2(rna_tf32(vlo.y), rna_tf32(vhi.y));
            dst[2] = make_float2(rna_tf32(vlo.z), rna_tf32(vhi.z));
            dst[3] = make_float2(rna_tf32(vlo.w), rna_tf32(vhi.w));
        }
    }
    // ---- A tile (EXACT values; rounded at fragment load)
    if (LAYER == 0) {
        // x rows [b][k] -> sA[b][k]
#pragma unroll
        for (int i = 0; i < 16; i++) {
            int idx = i * THR + t;          // 4096 float4 = 256 b x 16 k4
            int b = idx >> 4, k4 = idx & 15;
            float4 v = *(const float4*)(x + (size_t)(b0 + b) * 4096 + blk * 64 + k4 * 4);
            *(float4*)(sA + b * PAB + k4 * 4) = v;
        }
    } else {
        // g_S rows (blk*64 + k) are [k][b] -> sA[k][b]
#pragma unroll
        for (int i = 0; i < 16; i++) {
            int idx = i * THR + t;          // 4096 float4 = 64 k x 64 b4
            int k = idx >> 6, b4 = idx & 63;
            float4 v = *(const float4*)(g_S + ((size_t)blk * 64 + k) * BSZ + b0 + b4 * 4);
            *(float4*)(sA + k * PAK + b4 * 4) = v;
        }
    }
    __syncthreads();
    // ======= from here on: warps fully independent =======

    const int m0  = wid * 32;               // this warp's 32-row band
    const int r0a = m0 + g;                 // m-tile 0: rows r0a, r0a+8
    const int r0b = m0 + 16 + g;            // m-tile 1: rows r0b, r0b+8

    // ---- GEMM1 A-fragments (rounded once): au[mt][kt][4]
    uint32_t au[2][8][4];
#pragma unroll
    for (int kt = 0; kt < 8; kt++) {
        int k = kt * 8 + tig;
        if (LAYER == 0) {
            au[0][kt][0] = f2tf(sA[r0a * PAB + k]);
            au[0][kt][1] = f2tf(sA[(r0a + 8) * PAB + k]);
            au[0][kt][2] = f2tf(sA[r0a * PAB + k + 4]);
            au[0][kt][3] = f2tf(sA[(r0a + 8) * PAB + k + 4]);
            au[1][kt][0] = f2tf(sA[r0b * PAB + k]);
            au[1][kt][1] = f2tf(sA[(r0b + 8) * PAB + k]);
            au[1][kt][2] = f2tf(sA[r0b * PAB + k + 4]);
            au[1][kt][3] = f2tf(sA[(r0b + 8) * PAB + k + 4]);
        } else {
            au[0][kt][0] = f2tf(sA[k * PAK + r0a]);
            au[0][kt][1] = f2tf(sA[k * PAK + r0a + 8]);
            au[0][kt][2] = f2tf(sA[(k + 4) * PAK + r0a]);
            au[0][kt][3] = f2tf(sA[(k + 4) * PAK + r0a + 8]);
            au[1][kt][0] = f2tf(sA[k * PAK + r0b]);
            au[1][kt][1] = f2tf(sA[k * PAK + r0b + 8]);
            au[1][kt][2] = f2tf(sA[(k + 4) * PAK + r0b]);
            au[1][kt][3] = f2tf(sA[(k + 4) * PAK + r0b + 8]);
        }
    }

    // ---- Fused GEMM1 -> ELU -> GEMM2 over 16 e-blocks
    float acc2[2][8][4];
#pragma unroll
    for (int mt = 0; mt < 2; mt++)
#pragma unroll
        for (int nt = 0; nt < 8; nt++)
#pragma unroll
            for (int c = 0; c < 4; c++) acc2[mt][nt][c] = 0.f;

    const int qbase = lane & ~3;            // quad base lane
    const int s0 = qbase | (tig >> 1);      // src lane for col tig
    const int s2 = s0 | 2;                  // src lane for col tig+4
    const bool odd = (tig & 1);

#pragma unroll
    for (int kb = 0; kb < 16; kb++) {
        // GEMM1 slice: C1[32 x 8] for e-block kb
        float a1[2][4] = {{0.f, 0.f, 0.f, 0.f}, {0.f, 0.f, 0.f, 0.f}};
#pragma unroll
        for (int kt = 0; kt < 8; kt++) {
            float2 w = sW1p[(kt * 4 + tig) * PW1P + kb * 8 + g];
            uint32_t w0 = __float_as_uint(w.x), w1v = __float_as_uint(w.y);
            mma8(a1[0], au[0][kt], w0, w1v);
            mma8(a1[1], au[1][kt], w0, w1v);
        }

        // bias + ELU + round + quad-shuffle C-frag -> A-frag, both m-tiles
        float bb0 = sb1[kb * 8 + tig * 2];
        float bb1 = sb1[kb * 8 + tig * 2 + 1];
        uint32_t a2f[2][4];
#pragma unroll
        for (int mt = 0; mt < 2; mt++) {
            float h0 = a1[mt][0] + bb0;     // (r,   2tig)
            float h1 = a1[mt][1] + bb1;     // (r,   2tig+1)
            float h2 = a1[mt][2] + bb0;     // (r+8, 2tig)
            float h3 = a1[mt][3] + bb1;     // (r+8, 2tig+1)
            h0 = rna_tf32(h0 > 0.f ? h0 : (__expf(h0) - 1.f));
            h1 = rna_tf32(h1 > 0.f ? h1 : (__expf(h1) - 1.f));
            h2 = rna_tf32(h2 > 0.f ? h2 : (__expf(h2) - 1.f));
            h3 = rna_tf32(h3 > 0.f ? h3 : (__expf(h3) - 1.f));

            float p0 = __shfl_sync(0xffffffffu, h0, s0);
            float p1 = __shfl_sync(0xffffffffu, h1, s0);
            float q0 = __shfl_sync(0xffffffffu, h2, s0);
            float q1 = __shfl_sync(0xffffffffu, h3, s0);
            float r0f = __shfl_sync(0xffffffffu, h0, s2);
            float r1f = __shfl_sync(0xffffffffu, h1, s2);
            float u0 = __shfl_sync(0xffffffffu, h2, s2);
            float u1 = __shfl_sync(0xffffffffu, h3, s2);
            a2f[mt][0] = __float_as_uint(odd ? p1 : p0);   // (r,   tig)
            a2f[mt][1] = __float_as_uint(odd ? q1 : q0);   // (r+8, tig)
            a2f[mt][2] = __float_as_uint(odd ? r1f : r0f); // (r,   tig+4)
            a2f[mt][3] = __float_as_uint(odd ? u1 : u0);   // (r+8, tig+4)
        }

        // GEMM2 accumulate: k-block = kb
#pragma unroll
        for (int nt = 0; nt < 8; nt++) {
            float2 w = sW2p[(kb * 4 + tig) * PW2P + nt * 8 + g];
            uint32_t w0 = __float_as_uint(w.x), w1v = __float_as_uint(w.y);
            mma8(acc2[0][nt], a2f[0], w0, w1v);
            mma8(acc2[1][nt], a2f[1], w0, w1v);
        }
    }

    // ---- Epilogue: bias + residual (exact z from sA) + stores
#pragma unroll
    for (int mt = 0; mt < 2; mt++) {
        const int rbase = m0 + mt * 16 + g;
#pragma unroll
        for (int nt = 0; nt < 8; nt++) {
#pragma unroll
            for (int c = 0; c < 4; c++) {
                int row = rbase + 8 * (c >> 1);
                int d   = nt * 8 + tig * 2 + (c & 1);
                float z = (LAYER == 0) ? sA[row * PAB + d] : sA[d * PAK + row];
                float v = acc2[mt][nt][c] + sb2[d] + z;
                if (LAYER == 0)
                    g_S [((size_t)d * 64 + blk) * BSZ + b0 + row] = v;   // [d][m=blk][b]
                else
                    g_S2[((size_t)d * 64 + blk) * BSZ + b0 + row] = v;   // [f][b]
            }
        }
    }
}

// ---------------------------------------------------------------------------
// Final transpose: out[b][f] = g_S2[f][b]   (4096 x 8192 -> 8192 x 4096)
// ---------------------------------------------------------------------------
__global__ void __launch_bounds__(256)
transpose_kernel(float* __restrict__ out) {
    __shared__ float tile[64 * 68];
    const int f0 = blockIdx.x * 64, bb0 = blockIdx.y * 64;
    const int t = threadIdx.x;
#pragma unroll
    for (int p = 0; p < 4; p++) {
        int idx = p * 256 + t;              // 1024 float4 = 64 f x 16 b4
        int f = idx >> 4, b4 = idx & 15;
        float4 v = *(const float4*)(g_S2 + (size_t)(f0 + f) * BSZ + bb0 + b4 * 4);
        float* d = tile + f * 68 + b4 * 4;
        d[0] = v.x; d[1] = v.y; d[2] = v.z; d[3] = v.w;
    }
    __syncthreads();
#pragma unroll
    for (int p = 0; p < 4; p++) {
        int idx = p * 256 + t;              // 1024 float4 = 64 b x 16 f4
        int b = idx >> 4, f4 = idx & 15;
        float4 v;
        v.x = tile[(f4 * 4 + 0) * 68 + b];
        v.y = tile[(f4 * 4 + 1) * 68 + b];
        v.z = tile[(f4 * 4 + 2) * 68 + b];
        v.w = tile[(f4 * 4 + 3) * 68 + b];
        *(float4*)(out + (size_t)(bb0 + b) * 4096 + f0 + f4 * 4) = v;
    }
}

// ---------------------------------------------------------------------------
// kernel_launch
// ---------------------------------------------------------------------------
extern "C" void kernel_launch(void* const* d_in, const int* in_sizes, int n_in,
                              void* d_out, int out_size) {
    const float* x  = (const float*)d_in[0];
    const float* w1 = (const float*)d_in[1];
    const float* b1 = (const float*)d_in[2];
    const float* w2 = (const float*)d_in[3];
    const float* b2 = (const float*)d_in[4];
    float* out = (float*)d_out;
    (void)in_sizes; (void)n_in; (void)out_size;

    cudaFuncSetAttribute(layer_kernel<0>, cudaFuncAttributeMaxDynamicSharedMemorySize, SMEM_BYTES);
    cudaFuncSetAttribute(layer_kernel<1>, cudaFuncAttributeMaxDynamicSharedMemorySize, SMEM_BYTES);

    layer_kernel<0><<<dim3(32, 64), THR, SMEM_BYTES>>>(x, w1, b1, w2, b2);
    layer_kernel<1><<<dim3(32, 64), THR, SMEM_BYTES>>>(x, w1, b1, w2, b2);
    transpose_kernel<<<dim3(64, 128), 256>>>(out);
}